// round 12
// baseline (speedup 1.0000x reference)
#include <cuda_runtime.h>
#include <cuda_fp16.h>
#include <cstdint>

#define N_NODES 50000
#define N_EDGES 600000
#define D 128
#define SCAN_BLK 1024
#define NB ((N_NODES + SCAN_BLK - 1) / SCAN_BLK)   // 49
#define S 132   // smem row stride (floats) to avoid bank conflicts

// ---------------------------------------------------------------------------
// Scratch (device globals: allocation-free, graph-capturable)
// ---------------------------------------------------------------------------
__device__ int    g_deg_i[N_NODES];
__device__ int    g_cursor[N_NODES];
__device__ int    g_off[N_NODES];
__device__ int    g_counter;
__device__ int    g_eidx[N_EDGES];      // src index per edge, CSR order
__device__ float  g_norm[N_NODES];
__device__ __half g_hs[N_NODES * D];    // norm-prescaled layer-1 input (fp16)
__device__ __half g_h1[N_NODES * D];    // norm-prescaled relu output (fp16)
__device__ __half g_agg[N_NODES * D];   // aggregate (fp16)

// ---------------------------------------------------------------------------
// CSR build
// ---------------------------------------------------------------------------
__global__ void zero_kernel() {
    int i = blockIdx.x * blockDim.x + threadIdx.x;
    if (i < N_NODES) g_deg_i[i] = 0;
    if (i == 0) g_counter = 0;
}

__global__ void hist_kernel(const int4* __restrict__ dst4) {
    int i = blockIdx.x * blockDim.x + threadIdx.x;
    if (i < N_EDGES / 4) {
        int4 d = __ldg(&dst4[i]);
        atomicAdd(&g_deg_i[d.x], 1);
        atomicAdd(&g_deg_i[d.y], 1);
        atomicAdd(&g_deg_i[d.z], 1);
        atomicAdd(&g_deg_i[d.w], 1);
    }
}

__device__ __forceinline__ int warp_incl_scan(int x, int lane) {
    #pragma unroll
    for (int ofs = 1; ofs < 32; ofs <<= 1) {
        int t = __shfl_up_sync(0xFFFFFFFFu, x, ofs);
        if (lane >= ofs) x += t;
    }
    return x;
}

// Scan (block-local prefix + atomic base) FUSED with norm + feature prescale.
// Block b owns nodes [b*1024, b*1024+1024): computes offsets/cursor/norm,
// then prescales those nodes' feature rows into fp16 g_hs.
__global__ __launch_bounds__(SCAN_BLK) void scan_prescale_kernel(
    const float4* __restrict__ f) {
    __shared__ int   wsum[32];
    __shared__ int   base_s;
    __shared__ float s_norm[SCAN_BLK];
    int tid = threadIdx.x, lane = tid & 31, wid = tid >> 5;
    int node0 = blockIdx.x * SCAN_BLK;
    int idx = node0 + tid;

    int v = (idx < N_NODES) ? g_deg_i[idx] : 0;
    int incl = warp_incl_scan(v, lane);
    if (lane == 31) wsum[wid] = incl;
    __syncthreads();
    if (wid == 0) {
        int s = wsum[lane];
        int si = warp_incl_scan(s, lane);
        wsum[lane] = si - s;
    }
    __syncthreads();
    incl += wsum[wid];
    if (tid == SCAN_BLK - 1) base_s = atomicAdd(&g_counter, incl);

    float nm = rsqrtf(fmaxf((float)v, 1.0f));
    s_norm[tid] = nm;
    __syncthreads();

    if (idx < N_NODES) {
        int excl = base_s + incl - v;
        g_off[idx]    = excl;
        g_cursor[idx] = excl;
        g_norm[idx]   = nm;
    }

    // Prescale this block's 1024 feature rows -> fp16 (coalesced float4).
    int nrows = N_NODES - node0;
    if (nrows > SCAN_BLK) nrows = SCAN_BLK;
    int total = nrows * (D / 4);
    for (int j = tid; j < total; j += SCAN_BLK) {
        int rloc = j >> 5;
        int c4   = j & 31;
        float sc = s_norm[rloc];
        float4 x = __ldg(&f[(node0 + rloc) * 32 + c4]);
        half2 a = __floats2half2_rn(x.x * sc, x.y * sc);
        half2 b = __floats2half2_rn(x.z * sc, x.w * sc);
        uint2 u;
        u.x = *reinterpret_cast<unsigned*>(&a);
        u.y = *reinterpret_cast<unsigned*>(&b);
        reinterpret_cast<uint2*>(g_hs)[(node0 + rloc) * 32 + c4] = u;
    }
}

__global__ void fill_kernel(const int4* __restrict__ src4,
                            const int4* __restrict__ dst4) {
    int i = blockIdx.x * blockDim.x + threadIdx.x;
    if (i < N_EDGES / 4) {
        int4 s = __ldg(&src4[i]);
        int4 d = __ldg(&dst4[i]);
        int q0 = atomicAdd(&g_cursor[d.x], 1);
        int q1 = atomicAdd(&g_cursor[d.y], 1);
        int q2 = atomicAdd(&g_cursor[d.z], 1);
        int q3 = atomicAdd(&g_cursor[d.w], 1);
        g_eidx[q0] = s.x;
        g_eidx[q1] = s.y;
        g_eidx[q2] = s.z;
        g_eidx[q3] = s.w;
    }
}

// ---------------------------------------------------------------------------
// CSR aggregate: one warp per dst node (proven shape), fp16 rows (LDG.64),
// fp32 accumulation, fp16 output.  agg[n,:] = norm[n] * sum_e hs[src_e,:]
// ---------------------------------------------------------------------------
template <bool LAYER1>
__global__ __launch_bounds__(256) void aggregate_kernel() {
    int warp = (blockIdx.x * blockDim.x + threadIdx.x) >> 5;
    int lane = threadIdx.x & 31;
    if (warp >= N_NODES) return;
    const uint2* __restrict__ h = reinterpret_cast<const uint2*>(
        LAYER1 ? g_hs : g_h1);   // 32 uint2 per row

    int beg = g_off[warp];
    int end = beg + __ldg(&g_deg_i[warp]);

    float4 acc = make_float4(0.f, 0.f, 0.f, 0.f);

    for (int base = beg; base < end; base += 32) {
        int n = end - base;
        if (n > 32) n = 32;
        int idx = 0;
        if (lane < n) idx = __ldg(&g_eidx[base + lane]);  // coalesced
        int j = 0;
        for (; j + 4 <= n; j += 4) {
            int s0 = __shfl_sync(0xFFFFFFFFu, idx, j);
            int s1 = __shfl_sync(0xFFFFFFFFu, idx, j + 1);
            int s2 = __shfl_sync(0xFFFFFFFFu, idx, j + 2);
            int s3 = __shfl_sync(0xFFFFFFFFu, idx, j + 3);
            uint2 u0 = __ldg(&h[s0 * 32 + lane]);
            uint2 u1 = __ldg(&h[s1 * 32 + lane]);
            uint2 u2 = __ldg(&h[s2 * 32 + lane]);
            uint2 u3 = __ldg(&h[s3 * 32 + lane]);
            float2 a0 = __half22float2(*reinterpret_cast<half2*>(&u0.x));
            float2 b0 = __half22float2(*reinterpret_cast<half2*>(&u0.y));
            float2 a1 = __half22float2(*reinterpret_cast<half2*>(&u1.x));
            float2 b1 = __half22float2(*reinterpret_cast<half2*>(&u1.y));
            float2 a2 = __half22float2(*reinterpret_cast<half2*>(&u2.x));
            float2 b2 = __half22float2(*reinterpret_cast<half2*>(&u2.y));
            float2 a3 = __half22float2(*reinterpret_cast<half2*>(&u3.x));
            float2 b3 = __half22float2(*reinterpret_cast<half2*>(&u3.y));
            float tx0 = a0.x + a1.x, tx1 = a2.x + a3.x;
            float ty0 = a0.y + a1.y, ty1 = a2.y + a3.y;
            float tz0 = b0.x + b1.x, tz1 = b2.x + b3.x;
            float tw0 = b0.y + b1.y, tw1 = b2.y + b3.y;
            acc.x += tx0 + tx1;
            acc.y += ty0 + ty1;
            acc.z += tz0 + tz1;
            acc.w += tw0 + tw1;
        }
        for (; j < n; j++) {
            int s0 = __shfl_sync(0xFFFFFFFFu, idx, j);
            uint2 u0 = __ldg(&h[s0 * 32 + lane]);
            float2 a0 = __half22float2(*reinterpret_cast<half2*>(&u0.x));
            float2 b0 = __half22float2(*reinterpret_cast<half2*>(&u0.y));
            acc.x += a0.x; acc.y += a0.y; acc.z += b0.x; acc.w += b0.y;
        }
    }
    float dn = g_norm[warp];
    half2 o1 = __floats2half2_rn(acc.x * dn, acc.y * dn);
    half2 o2 = __floats2half2_rn(acc.z * dn, acc.w * dn);
    uint2 u;
    u.x = *reinterpret_cast<unsigned*>(&o1);
    u.y = *reinterpret_cast<unsigned*>(&o2);
    reinterpret_cast<uint2*>(g_agg)[warp * 32 + lane] = u;
}

// ---------------------------------------------------------------------------
// TF32 helpers
// ---------------------------------------------------------------------------
__device__ __forceinline__ unsigned f2tf32(float x) {
    unsigned r;
    asm("cvt.rna.tf32.f32 %0, %1;" : "=r"(r) : "f"(x));
    return r;
}

__device__ __forceinline__ void mma_tf32(float* d, const unsigned* a,
                                         const unsigned* b) {
    asm("mma.sync.aligned.m16n8k8.row.col.f32.tf32.tf32.f32 "
        "{%0,%1,%2,%3}, {%4,%5,%6,%7}, {%8,%9}, {%0,%1,%2,%3};"
        : "+f"(d[0]), "+f"(d[1]), "+f"(d[2]), "+f"(d[3])
        : "r"(a[0]), "r"(a[1]), "r"(a[2]), "r"(a[3]), "r"(b[0]), "r"(b[1]));
}

// ---------------------------------------------------------------------------
// Epilogue GEMM on tensor cores (tf32, proven layout), fp16 agg input:
//   LAYER1: h1 = half( norm (.) relu(agg @ W + b) )
//   else:   out = agg @ W + b   (fp32)
// ---------------------------------------------------------------------------
template <bool LAYER1>
__global__ __launch_bounds__(256) void epilogue_kernel(
    const float* __restrict__ W, const float* __restrict__ bias,
    float* __restrict__ outp) {
    extern __shared__ float smem[];
    float* sWt = smem;           // [128 n][S]  (k contiguous)
    float* sH  = smem + D * S;   // [128 m][S]  (k contiguous)

    int tid  = threadIdx.x;
    int lane = tid & 31;
    int warp = tid >> 5;
    int warpM = warp & 3;
    int warpN = warp >> 2;
    int g = lane >> 2;
    int t = lane & 3;
    int row0 = blockIdx.x * 128;

    for (int i = tid; i < D * D / 4; i += 256) {
        int k  = i >> 5;
        int n0 = (i & 31) * 4;
        float4 w = __ldg(&reinterpret_cast<const float4*>(W)[i]);
        sWt[(n0 + 0) * S + k] = __uint_as_float(f2tf32(w.x));
        sWt[(n0 + 1) * S + k] = __uint_as_float(f2tf32(w.y));
        sWt[(n0 + 2) * S + k] = __uint_as_float(f2tf32(w.z));
        sWt[(n0 + 3) * S + k] = __uint_as_float(f2tf32(w.w));
    }

    for (int i = tid; i < 128 * (D / 4); i += 256) {
        int r  = i >> 5;
        int c4 = i & 31;
        int node = row0 + r;
        float2 a = make_float2(0.f, 0.f), b = make_float2(0.f, 0.f);
        if (node < N_NODES) {
            uint2 u = reinterpret_cast<const uint2*>(g_agg)[node * 32 + c4];
            a = __half22float2(*reinterpret_cast<half2*>(&u.x));
            b = __half22float2(*reinterpret_cast<half2*>(&u.y));
        }
        float* p = &sH[r * S + c4 * 4];
        p[0] = __uint_as_float(f2tf32(a.x));
        p[1] = __uint_as_float(f2tf32(a.y));
        p[2] = __uint_as_float(f2tf32(b.x));
        p[3] = __uint_as_float(f2tf32(b.y));
    }
    __syncthreads();

    float acc[2][8][4];
    #pragma unroll
    for (int mi = 0; mi < 2; mi++)
        #pragma unroll
        for (int ni = 0; ni < 8; ni++)
            #pragma unroll
            for (int c = 0; c < 4; c++) acc[mi][ni][c] = 0.f;

    #pragma unroll 4
    for (int kt = 0; kt < 16; kt++) {
        int k0 = kt * 8;
        unsigned a[2][4];
        #pragma unroll
        for (int mi = 0; mi < 2; mi++) {
            int R = warpM * 32 + mi * 16;
            a[mi][0] = __float_as_uint(sH[(R + g)     * S + k0 + t]);
            a[mi][1] = __float_as_uint(sH[(R + g + 8) * S + k0 + t]);
            a[mi][2] = __float_as_uint(sH[(R + g)     * S + k0 + t + 4]);
            a[mi][3] = __float_as_uint(sH[(R + g + 8) * S + k0 + t + 4]);
        }
        #pragma unroll
        for (int ni = 0; ni < 8; ni++) {
            int C = warpN * 64 + ni * 8;
            unsigned b[2];
            b[0] = __float_as_uint(sWt[(C + g) * S + k0 + t]);
            b[1] = __float_as_uint(sWt[(C + g) * S + k0 + t + 4]);
            mma_tf32(acc[0][ni], a[0], b);
            mma_tf32(acc[1][ni], a[1], b);
        }
    }

    float nmA[2] = {1.f, 1.f}, nmB[2] = {1.f, 1.f};
    if (LAYER1) {
        #pragma unroll
        for (int mi = 0; mi < 2; mi++) {
            int r1 = row0 + warpM * 32 + mi * 16 + g;
            int r2 = r1 + 8;
            nmA[mi] = (r1 < N_NODES) ? g_norm[r1] : 0.f;
            nmB[mi] = (r2 < N_NODES) ? g_norm[r2] : 0.f;
        }
    }

    #pragma unroll
    for (int ni = 0; ni < 8; ni++) {
        int c = warpN * 64 + ni * 8 + 2 * t;
        float2 bb = *reinterpret_cast<const float2*>(&bias[c]);
        #pragma unroll
        for (int mi = 0; mi < 2; mi++) {
            int r1 = row0 + warpM * 32 + mi * 16 + g;
            int r2 = r1 + 8;
            float2 o1 = make_float2(acc[mi][ni][0] + bb.x,
                                    acc[mi][ni][1] + bb.y);
            float2 o2 = make_float2(acc[mi][ni][2] + bb.x,
                                    acc[mi][ni][3] + bb.y);
            if (LAYER1) {
                o1.x = fmaxf(o1.x, 0.f) * nmA[mi];
                o1.y = fmaxf(o1.y, 0.f) * nmA[mi];
                o2.x = fmaxf(o2.x, 0.f) * nmB[mi];
                o2.y = fmaxf(o2.y, 0.f) * nmB[mi];
                if (r1 < N_NODES)
                    *reinterpret_cast<half2*>(&g_h1[r1 * D + c]) =
                        __floats2half2_rn(o1.x, o1.y);
                if (r2 < N_NODES)
                    *reinterpret_cast<half2*>(&g_h1[r2 * D + c]) =
                        __floats2half2_rn(o2.x, o2.y);
            } else {
                if (r1 < N_NODES)
                    *reinterpret_cast<float2*>(&outp[r1 * D + c]) = o1;
                if (r2 < N_NODES)
                    *reinterpret_cast<float2*>(&outp[r2 * D + c]) = o2;
            }
        }
    }
}

// ---------------------------------------------------------------------------
// Launch
// ---------------------------------------------------------------------------
extern "C" void kernel_launch(void* const* d_in, const int* in_sizes, int n_in,
                              void* d_out, int out_size) {
    const float* features = (const float*)d_in[0];
    const int*   src      = (const int*)d_in[1];
    const int*   dst      = (const int*)d_in[2];
    const float* W0       = (const float*)d_in[3];
    const float* b0       = (const float*)d_in[4];
    const float* W1       = (const float*)d_in[5];
    const float* b1       = (const float*)d_in[6];
    float* out = (float*)d_out;

    const int SMEM_EPI = 2 * D * S * sizeof(float);  // 135168 B
    cudaFuncSetAttribute(epilogue_kernel<true>,
                         cudaFuncAttributeMaxDynamicSharedMemorySize, SMEM_EPI);
    cudaFuncSetAttribute(epilogue_kernel<false>,
                         cudaFuncAttributeMaxDynamicSharedMemorySize, SMEM_EPI);

    const int nodesBlocks = (N_NODES + 255) / 256;
    const int edge4Blocks = (N_EDGES / 4 + 255) / 256;
    const int aggBlocks   = (N_NODES + 7) / 8;
    const int epiBlocks   = (N_NODES + 127) / 128;

    // CSR build + prescale (4 launches)
    zero_kernel<<<nodesBlocks, 256>>>();
    hist_kernel<<<edge4Blocks, 256>>>((const int4*)dst);
    scan_prescale_kernel<<<NB, SCAN_BLK>>>((const float4*)features);
    fill_kernel<<<edge4Blocks, 256>>>((const int4*)src, (const int4*)dst);

    // Layer 1
    aggregate_kernel<true><<<aggBlocks, 256>>>();
    epilogue_kernel<true><<<epiBlocks, 256, SMEM_EPI>>>(W0, b0, nullptr);

    // Layer 2
    aggregate_kernel<false><<<aggBlocks, 256>>>();
    epilogue_kernel<false><<<epiBlocks, 256, SMEM_EPI>>>(W1, b1, out);
}

// round 13
// speedup vs baseline: 1.2099x; 1.2099x over previous
#include <cuda_runtime.h>
#include <cuda_fp16.h>
#include <cstdint>

#define N_NODES 50000
#define N_EDGES 600000
#define D 128
#define SCAN_BLK 1024
#define NB ((N_NODES + SCAN_BLK - 1) / SCAN_BLK)   // 49
#define SK 136   // smem row stride in HALVES (68 words; 68%32=4 -> conflict-free frags)

// ---------------------------------------------------------------------------
// Scratch (device globals: allocation-free, graph-capturable)
// ---------------------------------------------------------------------------
__device__ int    g_deg_i[N_NODES];
__device__ int    g_cursor[N_NODES];
__device__ int    g_off[N_NODES];
__device__ int    g_counter;
__device__ int    g_eidx[N_EDGES];      // src index per edge, CSR order
__device__ float  g_norm[N_NODES];
__device__ __half g_hs[N_NODES * D];    // norm-prescaled layer-1 input (fp16)
__device__ __half g_h1[N_NODES * D];    // norm-prescaled relu output (fp16)
__device__ __half g_agg[N_NODES * D];   // aggregate (fp16)

// ---------------------------------------------------------------------------
// CSR build (round-11 proven kernels)
// ---------------------------------------------------------------------------
__global__ void zero_kernel() {
    int i = blockIdx.x * blockDim.x + threadIdx.x;
    if (i < N_NODES) g_deg_i[i] = 0;
    if (i == 0) g_counter = 0;
}

__global__ void hist_kernel(const int4* __restrict__ dst4) {
    int i = blockIdx.x * blockDim.x + threadIdx.x;
    if (i < N_EDGES / 4) {
        int4 d = __ldg(&dst4[i]);
        atomicAdd(&g_deg_i[d.x], 1);
        atomicAdd(&g_deg_i[d.y], 1);
        atomicAdd(&g_deg_i[d.z], 1);
        atomicAdd(&g_deg_i[d.w], 1);
    }
}

__device__ __forceinline__ int warp_incl_scan(int x, int lane) {
    #pragma unroll
    for (int ofs = 1; ofs < 32; ofs <<= 1) {
        int t = __shfl_up_sync(0xFFFFFFFFu, x, ofs);
        if (lane >= ofs) x += t;
    }
    return x;
}

__global__ __launch_bounds__(SCAN_BLK) void scan_kernel() {
    __shared__ int wsum[32];
    __shared__ int base_s;
    int tid = threadIdx.x, lane = tid & 31, wid = tid >> 5;
    int idx = blockIdx.x * SCAN_BLK + tid;

    int v = (idx < N_NODES) ? g_deg_i[idx] : 0;
    int incl = warp_incl_scan(v, lane);
    if (lane == 31) wsum[wid] = incl;
    __syncthreads();
    if (wid == 0) {
        int s = wsum[lane];
        int si = warp_incl_scan(s, lane);
        wsum[lane] = si - s;
    }
    __syncthreads();
    incl += wsum[wid];
    if (tid == SCAN_BLK - 1) base_s = atomicAdd(&g_counter, incl);
    __syncthreads();

    if (idx < N_NODES) {
        int excl = base_s + incl - v;
        g_off[idx]    = excl;
        g_cursor[idx] = excl;
        g_norm[idx]   = rsqrtf(fmaxf((float)v, 1.0f));
    }
}

__global__ void fill_kernel(const int4* __restrict__ src4,
                            const int4* __restrict__ dst4) {
    int i = blockIdx.x * blockDim.x + threadIdx.x;
    if (i < N_EDGES / 4) {
        int4 s = __ldg(&src4[i]);
        int4 d = __ldg(&dst4[i]);
        int q0 = atomicAdd(&g_cursor[d.x], 1);
        int q1 = atomicAdd(&g_cursor[d.y], 1);
        int q2 = atomicAdd(&g_cursor[d.z], 1);
        int q3 = atomicAdd(&g_cursor[d.w], 1);
        g_eidx[q0] = s.x;
        g_eidx[q1] = s.y;
        g_eidx[q2] = s.z;
        g_eidx[q3] = s.w;
    }
}

// Prescale features by node norm -> fp16 (round-11 proven wide-grid kernel).
__global__ void prescale_kernel(const float4* __restrict__ f) {
    int i = blockIdx.x * blockDim.x + threadIdx.x;
    if (i < N_NODES * (D / 4)) {
        float nm = g_norm[i >> 5];
        float4 v = __ldg(&f[i]);
        half2 a = __floats2half2_rn(v.x * nm, v.y * nm);
        half2 b = __floats2half2_rn(v.z * nm, v.w * nm);
        uint2 u;
        u.x = *reinterpret_cast<unsigned*>(&a);
        u.y = *reinterpret_cast<unsigned*>(&b);
        reinterpret_cast<uint2*>(g_hs)[i] = u;
    }
}

// ---------------------------------------------------------------------------
// CSR aggregate: one warp per dst node (proven shape), fp16 rows (LDG.64),
// fp32 accumulation, fp16 output.
// ---------------------------------------------------------------------------
template <bool LAYER1>
__global__ __launch_bounds__(256) void aggregate_kernel() {
    int warp = (blockIdx.x * blockDim.x + threadIdx.x) >> 5;
    int lane = threadIdx.x & 31;
    if (warp >= N_NODES) return;
    const uint2* __restrict__ h = reinterpret_cast<const uint2*>(
        LAYER1 ? g_hs : g_h1);

    int beg = g_off[warp];
    int end = beg + __ldg(&g_deg_i[warp]);

    float4 acc = make_float4(0.f, 0.f, 0.f, 0.f);

    for (int base = beg; base < end; base += 32) {
        int n = end - base;
        if (n > 32) n = 32;
        int idx = 0;
        if (lane < n) idx = __ldg(&g_eidx[base + lane]);
        int j = 0;
        for (; j + 4 <= n; j += 4) {
            int s0 = __shfl_sync(0xFFFFFFFFu, idx, j);
            int s1 = __shfl_sync(0xFFFFFFFFu, idx, j + 1);
            int s2 = __shfl_sync(0xFFFFFFFFu, idx, j + 2);
            int s3 = __shfl_sync(0xFFFFFFFFu, idx, j + 3);
            uint2 u0 = __ldg(&h[s0 * 32 + lane]);
            uint2 u1 = __ldg(&h[s1 * 32 + lane]);
            uint2 u2 = __ldg(&h[s2 * 32 + lane]);
            uint2 u3 = __ldg(&h[s3 * 32 + lane]);
            float2 a0 = __half22float2(*reinterpret_cast<half2*>(&u0.x));
            float2 b0 = __half22float2(*reinterpret_cast<half2*>(&u0.y));
            float2 a1 = __half22float2(*reinterpret_cast<half2*>(&u1.x));
            float2 b1 = __half22float2(*reinterpret_cast<half2*>(&u1.y));
            float2 a2 = __half22float2(*reinterpret_cast<half2*>(&u2.x));
            float2 b2 = __half22float2(*reinterpret_cast<half2*>(&u2.y));
            float2 a3 = __half22float2(*reinterpret_cast<half2*>(&u3.x));
            float2 b3 = __half22float2(*reinterpret_cast<half2*>(&u3.y));
            float tx0 = a0.x + a1.x, tx1 = a2.x + a3.x;
            float ty0 = a0.y + a1.y, ty1 = a2.y + a3.y;
            float tz0 = b0.x + b1.x, tz1 = b2.x + b3.x;
            float tw0 = b0.y + b1.y, tw1 = b2.y + b3.y;
            acc.x += tx0 + tx1;
            acc.y += ty0 + ty1;
            acc.z += tz0 + tz1;
            acc.w += tw0 + tw1;
        }
        for (; j < n; j++) {
            int s0 = __shfl_sync(0xFFFFFFFFu, idx, j);
            uint2 u0 = __ldg(&h[s0 * 32 + lane]);
            float2 a0 = __half22float2(*reinterpret_cast<half2*>(&u0.x));
            float2 b0 = __half22float2(*reinterpret_cast<half2*>(&u0.y));
            acc.x += a0.x; acc.y += a0.y; acc.z += b0.x; acc.w += b0.y;
        }
    }
    float dn = g_norm[warp];
    half2 o1 = __floats2half2_rn(acc.x * dn, acc.y * dn);
    half2 o2 = __floats2half2_rn(acc.z * dn, acc.w * dn);
    uint2 u;
    u.x = *reinterpret_cast<unsigned*>(&o1);
    u.y = *reinterpret_cast<unsigned*>(&o2);
    reinterpret_cast<uint2*>(g_agg)[warp * 32 + lane] = u;
}

// ---------------------------------------------------------------------------
// fp16 MMA: m16n8k16, fp32 accumulate.
// A (row-major m16k16, f16x2 regs): a0=(g,2t:2t+1) a1=(g+8,2t:2t+1)
//                                   a2=(g,2t+8:2t+9) a3=(g+8,2t+8:2t+9)
// B (col-major k16n8):              b0={B[2t][g],B[2t+1][g]} b1={B[2t+8][g],B[2t+9][g]}
// C (fp32): c0=(g,2t) c1=(g,2t+1) c2=(g+8,2t) c3=(g+8,2t+1)
// ---------------------------------------------------------------------------
__device__ __forceinline__ void mma_f16(float* d, const unsigned* a,
                                        const unsigned* b) {
    asm("mma.sync.aligned.m16n8k16.row.col.f32.f16.f16.f32 "
        "{%0,%1,%2,%3}, {%4,%5,%6,%7}, {%8,%9}, {%0,%1,%2,%3};"
        : "+f"(d[0]), "+f"(d[1]), "+f"(d[2]), "+f"(d[3])
        : "r"(a[0]), "r"(a[1]), "r"(a[2]), "r"(a[3]), "r"(b[0]), "r"(b[1]));
}

// ---------------------------------------------------------------------------
// Epilogue GEMM on tensor cores (fp16 inputs, fp32 accum):
//   LAYER1: h1 = half( norm (.) relu(agg @ W + b) )
//   else:   out = agg @ W + b   (fp32)
// Block: 128x128 tile, 256 threads (8 warps as 4x2), warp = 32 rows x 64 cols.
// smem: sWt = W^T fp16 [n][k], sH = agg fp16 [m][k], stride SK=136 halves.
// 68 KB total -> 2 CTAs/SM.
// ---------------------------------------------------------------------------
template <bool LAYER1>
__global__ __launch_bounds__(256) void epilogue_kernel(
    const float* __restrict__ W, const float* __restrict__ bias,
    float* __restrict__ outp) {
    extern __shared__ __half smem_h[];
    __half* sWt = smem_h;            // [128 n][SK]
    __half* sH  = smem_h + D * SK;   // [128 m][SK]

    int tid  = threadIdx.x;
    int lane = tid & 31;
    int warp = tid >> 5;
    int warpM = warp & 3;
    int warpN = warp >> 2;
    int g = lane >> 2;
    int t = lane & 3;
    int row0 = blockIdx.x * 128;

    // W [k][n] fp32 -> sWt[n][k] fp16 (coalesced float4 reads)
    for (int i = tid; i < D * D / 4; i += 256) {
        int k  = i >> 5;
        int n0 = (i & 31) * 4;
        float4 w = __ldg(&reinterpret_cast<const float4*>(W)[i]);
        sWt[(n0 + 0) * SK + k] = __float2half_rn(w.x);
        sWt[(n0 + 1) * SK + k] = __float2half_rn(w.y);
        sWt[(n0 + 2) * SK + k] = __float2half_rn(w.z);
        sWt[(n0 + 3) * SK + k] = __float2half_rn(w.w);
    }

    // agg fp16 -> sH[m][k] (uint2 = 4 halfs, contiguous k)
    for (int i = tid; i < 128 * (D / 4); i += 256) {
        int r  = i >> 5;
        int c4 = i & 31;
        int node = row0 + r;
        uint2 u = make_uint2(0u, 0u);
        if (node < N_NODES)
            u = reinterpret_cast<const uint2*>(g_agg)[node * 32 + c4];
        *reinterpret_cast<uint2*>(&sH[r * SK + c4 * 4]) = u;
    }
    __syncthreads();

    float acc[2][8][4];
    #pragma unroll
    for (int mi = 0; mi < 2; mi++)
        #pragma unroll
        for (int ni = 0; ni < 8; ni++)
            #pragma unroll
            for (int c = 0; c < 4; c++) acc[mi][ni][c] = 0.f;

    #pragma unroll
    for (int kt = 0; kt < 8; kt++) {
        int k0 = kt * 16;
        unsigned a[2][4];
        #pragma unroll
        for (int mi = 0; mi < 2; mi++) {
            int R = warpM * 32 + mi * 16;
            a[mi][0] = *reinterpret_cast<const unsigned*>(&sH[(R + g)     * SK + k0 + 2 * t]);
            a[mi][1] = *reinterpret_cast<const unsigned*>(&sH[(R + g + 8) * SK + k0 + 2 * t]);
            a[mi][2] = *reinterpret_cast<const unsigned*>(&sH[(R + g)     * SK + k0 + 2 * t + 8]);
            a[mi][3] = *reinterpret_cast<const unsigned*>(&sH[(R + g + 8) * SK + k0 + 2 * t + 8]);
        }
        #pragma unroll
        for (int ni = 0; ni < 8; ni++) {
            int C = warpN * 64 + ni * 8;
            unsigned b[2];
            b[0] = *reinterpret_cast<const unsigned*>(&sWt[(C + g) * SK + k0 + 2 * t]);
            b[1] = *reinterpret_cast<const unsigned*>(&sWt[(C + g) * SK + k0 + 2 * t + 8]);
            mma_f16(acc[0][ni], a[0], b);
            mma_f16(acc[1][ni], a[1], b);
        }
    }

    float nmA[2] = {1.f, 1.f}, nmB[2] = {1.f, 1.f};
    if (LAYER1) {
        #pragma unroll
        for (int mi = 0; mi < 2; mi++) {
            int r1 = row0 + warpM * 32 + mi * 16 + g;
            int r2 = r1 + 8;
            nmA[mi] = (r1 < N_NODES) ? g_norm[r1] : 0.f;
            nmB[mi] = (r2 < N_NODES) ? g_norm[r2] : 0.f;
        }
    }

    #pragma unroll
    for (int ni = 0; ni < 8; ni++) {
        int c = warpN * 64 + ni * 8 + 2 * t;
        float2 bb = *reinterpret_cast<const float2*>(&bias[c]);
        #pragma unroll
        for (int mi = 0; mi < 2; mi++) {
            int r1 = row0 + warpM * 32 + mi * 16 + g;
            int r2 = r1 + 8;
            float2 o1 = make_float2(acc[mi][ni][0] + bb.x,
                                    acc[mi][ni][1] + bb.y);
            float2 o2 = make_float2(acc[mi][ni][2] + bb.x,
                                    acc[mi][ni][3] + bb.y);
            if (LAYER1) {
                o1.x = fmaxf(o1.x, 0.f) * nmA[mi];
                o1.y = fmaxf(o1.y, 0.f) * nmA[mi];
                o2.x = fmaxf(o2.x, 0.f) * nmB[mi];
                o2.y = fmaxf(o2.y, 0.f) * nmB[mi];
                if (r1 < N_NODES)
                    *reinterpret_cast<half2*>(&g_h1[r1 * D + c]) =
                        __floats2half2_rn(o1.x, o1.y);
                if (r2 < N_NODES)
                    *reinterpret_cast<half2*>(&g_h1[r2 * D + c]) =
                        __floats2half2_rn(o2.x, o2.y);
            } else {
                if (r1 < N_NODES)
                    *reinterpret_cast<float2*>(&outp[r1 * D + c]) = o1;
                if (r2 < N_NODES)
                    *reinterpret_cast<float2*>(&outp[r2 * D + c]) = o2;
            }
        }
    }
}

// ---------------------------------------------------------------------------
// Launch
// ---------------------------------------------------------------------------
extern "C" void kernel_launch(void* const* d_in, const int* in_sizes, int n_in,
                              void* d_out, int out_size) {
    const float* features = (const float*)d_in[0];
    const int*   src      = (const int*)d_in[1];
    const int*   dst      = (const int*)d_in[2];
    const float* W0       = (const float*)d_in[3];
    const float* b0       = (const float*)d_in[4];
    const float* W1       = (const float*)d_in[5];
    const float* b1       = (const float*)d_in[6];
    float* out = (float*)d_out;

    const int SMEM_EPI = 2 * D * SK * sizeof(__half);  // 69632 B
    cudaFuncSetAttribute(epilogue_kernel<true>,
                         cudaFuncAttributeMaxDynamicSharedMemorySize, SMEM_EPI);
    cudaFuncSetAttribute(epilogue_kernel<false>,
                         cudaFuncAttributeMaxDynamicSharedMemorySize, SMEM_EPI);

    const int nodesBlocks = (N_NODES + 255) / 256;
    const int edge4Blocks = (N_EDGES / 4 + 255) / 256;
    const int vecBlocks   = (N_NODES * (D / 4) + 255) / 256;
    const int aggBlocks   = (N_NODES + 7) / 8;
    const int epiBlocks   = (N_NODES + 127) / 128;

    // CSR build + prescale (5 launches)
    zero_kernel<<<nodesBlocks, 256>>>();
    hist_kernel<<<edge4Blocks, 256>>>((const int4*)dst);
    scan_kernel<<<NB, SCAN_BLK>>>();
    fill_kernel<<<edge4Blocks, 256>>>((const int4*)src, (const int4*)dst);
    prescale_kernel<<<vecBlocks, 256>>>((const float4*)features);

    // Layer 1
    aggregate_kernel<true><<<aggBlocks, 256>>>();
    epilogue_kernel<true><<<epiBlocks, 256, SMEM_EPI>>>(W0, b0, nullptr);

    // Layer 2
    aggregate_kernel<false><<<aggBlocks, 256>>>();
    epilogue_kernel<false><<<epiBlocks, 256, SMEM_EPI>>>(W1, b1, out);
}